// round 11
// baseline (speedup 1.0000x reference)
#include <cuda_runtime.h>

#define BB      16
#define NN      25200
#define NCLS    80
#define ROWW    85
#define NBUCK   1024
#define CAP     1024
#define KSEL    640
#define MAXDET  300
#define MASKW   (CAP / 64)     // 16 u64 words
#define PAIRCAP 8192
#define TILE    128

// ---- static device scratch (no runtime allocation allowed) ----
__device__ float4 g_cbox[BB * NN];     // xyxy per anchor
__device__ float2 g_cmeta[BB * NN];    // (conf or -1, class as float)
__device__ int    g_hist[BB * NBUCK];  // zero-init; k_nms restores zeros
__device__ int    g_picks[BB * MAXDET];
__device__ int    g_kept[BB];

__device__ __forceinline__ unsigned su32(const void* p) {
    unsigned r;
    asm("{ .reg .u64 t; cvta.to.shared.u64 t, %1; cvt.u32.u64 %0, t; }"
        : "=r"(r) : "l"(p));
    return r;
}

// ------------------------------------------------------------------
// Preprocess: cp.async staging (128-anchor tiles, 5 blocks/SM), per-anchor
// class argmax, box decode, score histogram.
__global__ void __launch_bounds__(256) k_prep(const float* __restrict__ pred, int img0) {
    extern __shared__ float psm[];                 // 128*85 floats = 43520 B
    int b  = blockIdx.y + img0;
    int a0 = blockIdx.x * TILE;
    int rows = NN - a0; if (rows > TILE) rows = TILE;   // 128 or 112, both %4==0
    const float4* gp4 = (const float4*)(pred + ((size_t)b * NN + a0) * ROWW);
    int nvec = rows * ROWW / 4;
    unsigned sbase = su32(psm);
    for (int k = threadIdx.x; k < nvec; k += 256) {
        asm volatile("cp.async.cg.shared.global [%0], [%1], 16;"
                     :: "r"(sbase + k * 16), "l"(gp4 + k));
    }
    asm volatile("cp.async.commit_group;");
    asm volatile("cp.async.wait_group 0;" ::: "memory");
    __syncthreads();

    int t = threadIdx.x;
    if (t < rows) {
        const float* p = psm + t * ROWW;
        float cx = p[0], cy = p[1], w = p[2], h = p[3], obj = p[4];
        float best = -1.0f; int bj = 0;
#pragma unroll 8
        for (int c = 0; c < NCLS; c++) {
            float v = __fmul_rn(p[5 + c], obj);   // same rounding as reference
            if (v > best) { best = v; bj = c; }   // first-max tie-break
        }
        float hw = __fmul_rn(w, 0.5f), hh = __fmul_rn(h, 0.5f);
        float4 box = make_float4(__fsub_rn(cx, hw), __fsub_rn(cy, hh),
                                 __fadd_rn(cx, hw), __fadd_rn(cy, hh));
        bool valid = (obj > 0.25f) && (best > 0.25f);
        size_t g = (size_t)b * NN + a0 + t;
        g_cbox[g]  = box;
        g_cmeta[g] = make_float2(valid ? best : -1.0f, (float)bj);
        if (valid) {
            int bkt = (int)(best * 1024.0f);      // *1024 exact (pow2)
            if (bkt > NBUCK - 1) bkt = NBUCK - 1;
            atomicAdd(&g_hist[b * NBUCK + bkt], 1);
        }
    }
}

// ------------------------------------------------------------------
// Bitonic compare-exchange via shfl (element per thread), desc final order.
__device__ __forceinline__ unsigned long long casx(unsigned long long v,
                                                   int j, int k, int t) {
    unsigned long long o = __shfl_xor_sync(0xffffffffu, v, j);
    bool takemax = (((t & j) == 0) == ((t & k) == 0));
    return takemax ? (v > o ? v : o) : (v < o ? v : o);
}

// ------------------------------------------------------------------
// Fused per-image: hist cutoff -> compact -> hybrid bitonic sort ->
// sparse pairwise suppression (SMEM pair list) -> single-thread bitmap scan.
__global__ void __launch_bounds__(1024, 1) k_nms() {
    extern __shared__ char dynsm[];
    unsigned long long* keys    = (unsigned long long*)dynsm;                   // 8KB
    float4*             obox    = (float4*)(dynsm + CAP * 8);                   // 16KB
    unsigned char*      cls     = (unsigned char*)(dynsm + CAP * 8 + CAP * 16); // 1KB
    int*                pairs   = (int*)(dynsm + CAP * 8 + CAP * 16 + CAP);     // 32KB
    unsigned long long* rflagw  = (unsigned long long*)((char*)pairs + PAIRCAP * 4); // 128B
    unsigned long long* removed = rflagw + MASKW;                                    // 128B
    int* hist_sm = (int*)obox;   // alias: histogram staging before obox built
    __shared__ int s_thr, s_cnt, s_np;

    int b = blockIdx.x, t = threadIdx.x;
    if (t == 0) { s_cnt = 0; s_np = 0; }
    hist_sm[t] = g_hist[b * NBUCK + t];      // blockDim == NBUCK == 1024
    g_hist[b * NBUCK + t] = 0;               // restore zeros for next replay
    if (t < MASKW) { rflagw[t] = 0ULL; removed[t] = 0ULL; }
    __syncthreads();

    // --- cutoff: largest bucket k with suffix_sum(k) >= KSEL (bumped if > CAP)
    if (t < 32) {
        int total = 0, thr = 0;
        for (int c = 0; c < 32; c++) {
            int k = 1023 - (c * 32 + t);
            int s = hist_sm[k];
#pragma unroll
            for (int off = 1; off < 32; off <<= 1) {
                int u = __shfl_up_sync(0xffffffffu, s, off);
                if (t >= off) s += u;
            }
            int S = total + s;
            unsigned bal = __ballot_sync(0xffffffffu, S >= KSEL);
            if (bal) {
                int f  = __ffs(bal) - 1;
                int Sf = __shfl_sync(0xffffffffu, S, f);
                int kk = 1023 - (c * 32 + f);
                thr = (Sf > CAP) ? kk + 1 : kk;
                break;
            }
            total = __shfl_sync(0xffffffffu, S, 31);
        }
        if (t == 0) s_thr = thr;
    }
    __syncthreads();
    int thr = s_thr;

    // --- compact: keys = (score_bits << 32) | ~anchor
    for (int a = t; a < NN; a += 1024) {
        float2 m = g_cmeta[(size_t)b * NN + a];
        if (m.x > 0.0f) {
            int bkt = (int)(m.x * 1024.0f);
            if (bkt > NBUCK - 1) bkt = NBUCK - 1;
            if (bkt >= thr) {
                int p = atomicAdd(&s_cnt, 1);
                if (p < CAP)
                    keys[p] = ((unsigned long long)__float_as_uint(m.x) << 32) |
                              (unsigned long long)(~(unsigned)a);
            }
        }
    }
    __syncthreads();
    int M = s_cnt; if (M > CAP) M = CAP;
    if (t >= M) keys[t] = 0ULL;
    __syncthreads();

    // --- hybrid bitonic sort: shfl for j<32, SMEM+barrier for j>=32
    {
        unsigned long long v = keys[t];
#pragma unroll
        for (int k = 2; k <= 32; k <<= 1)
#pragma unroll
            for (int j = k >> 1; j >= 1; j >>= 1)
                v = casx(v, j, k, t);
        for (int k = 64; k <= CAP; k <<= 1) {
            keys[t] = v;
            __syncthreads();
            for (int j = k >> 1; j >= 32; j >>= 1) {
                int i = t, l = i ^ j;
                if (l > i) {
                    unsigned long long x = keys[i], y = keys[l];
                    if ((x < y) == ((i & k) == 0)) { keys[i] = y; keys[l] = x; }
                }
                __syncthreads();
            }
            v = keys[t];
#pragma unroll
            for (int j = 16; j >= 1; j >>= 1)
                v = casx(v, j, k, t);
        }
        keys[t] = v;
    }
    __syncthreads();

    // --- build offset boxes / class
    if (t < M) {
        unsigned anc = ~(unsigned)(keys[t] & 0xFFFFFFFFULL);
        size_t g = (size_t)b * NN + anc;
        float4 bx = g_cbox[g];
        float  jf = g_cmeta[g].y;
        float off = jf * 4096.0f;   // exact
        obox[t] = make_float4(__fadd_rn(bx.x, off), __fadd_rn(bx.y, off),
                              __fadd_rn(bx.z, off), __fadd_rn(bx.w, off));
        cls[t] = (unsigned char)(int)jf;
    }
    __syncthreads();

    // --- sparse pairwise suppression: thread i scans j>i of same class; any
    //     IoU>0.45 pair appended to SMEM list; rflag bit set for row i.
#define CHECKJ(jj) do { \
        float4 bj = obox[jj]; \
        float ltx = fmaxf(bi.x, bj.x), lty = fmaxf(bi.y, bj.y); \
        float rbx = fminf(bi.z, bj.z), rby = fminf(bi.w, bj.w); \
        float ww = fmaxf(__fsub_rn(rbx, ltx), 0.0f); \
        float hh = fmaxf(__fsub_rn(rby, lty), 0.0f); \
        float inter = __fmul_rn(ww, hh); \
        float a2 = __fmul_rn(__fsub_rn(bj.z, bj.x), __fsub_rn(bj.w, bj.y)); \
        float den = __fadd_rn(__fsub_rn(__fadd_rn(a1, a2), inter), 1e-9f); \
        if (__fdiv_rn(inter, den) > 0.45f) { \
            int p = atomicAdd(&s_np, 1); \
            if (p < PAIRCAP) pairs[p] = (i << 10) | (jj); \
            any = 1; \
        } \
    } while (0)

    if (t < M) {
        int i = t;
        unsigned char ci = cls[i];
        float4 bi = obox[i];
        float a1 = __fmul_rn(__fsub_rn(bi.z, bi.x), __fsub_rn(bi.w, bi.y));
        unsigned cw = (unsigned)ci * 0x01010101u;
        int any = 0;
        int j = i + 1;
        while (j < M && (j & 3)) { if (cls[j] == ci) CHECKJ(j); j++; }
        const unsigned* c32 = (const unsigned*)cls;
        for (; j + 4 <= M; j += 4) {
            unsigned w4 = c32[j >> 2];
            unsigned eq = __vcmpeq4(w4, cw);
            if (eq) {
                if (eq & 0x000000ffu) CHECKJ(j);
                if (eq & 0x0000ff00u) CHECKJ(j + 1);
                if (eq & 0x00ff0000u) CHECKJ(j + 2);
                if (eq & 0xff000000u) CHECKJ(j + 3);
            }
        }
        while (j < M) { if (cls[j] == ci) CHECKJ(j); j++; }
        if (any)
            atomicOr(rflagw + (i >> 6), 1ULL << (i & 63));
    }
#undef CHECKJ
    __syncthreads();

    // --- single-thread greedy scan over 64-index chunks (register bit tests;
    //     pair application + chunk refresh only on the rare suppressing pick)
    if (t == 0) {
        int P = s_np; if (P > PAIRCAP) P = PAIRCAP;
        int nk = 0;
        const unsigned* klo = (const unsigned*)keys;   // little-endian low word
        for (int c = 0; c * 64 < M && nk < MAXDET; c++) {
            unsigned long long rem = removed[c];
            unsigned long long rfl = rflagw[c];
            int base = c * 64;
            int lim = M - base; if (lim > 64) lim = 64;
            for (int x = 0; x < lim; x++) {
                if ((rem >> x) & 1ULL) continue;
                int i = base + x;
                g_picks[b * MAXDET + nk] = (int)~klo[2 * i];
                nk++;
                if (nk == MAXDET) break;
                if ((rfl >> x) & 1ULL) {
                    for (int e = 0; e < P; e++) {
                        int pr = pairs[e];
                        if ((pr >> 10) == i) {
                            int jj = pr & 1023;
                            removed[jj >> 6] |= 1ULL << (jj & 63);
                        }
                    }
                    rem = removed[c];   // refresh current chunk
                }
            }
        }
        g_kept[b] = nk;
    }
}

// ------------------------------------------------------------------
// Output: [dets (B,300,6)] [lg (B,300,80)] [keep (B,300)] as float32.
// One warp per detection row.
__global__ void __launch_bounds__(256) k_out(const float* __restrict__ logits,
                                             float* __restrict__ out) {
    int row  = blockIdx.x * 8 + (threadIdx.x >> 5);   // 0..4799
    int lane = threadIdx.x & 31;
    int b = row / MAXDET, r = row % MAXDET;
    bool on = (r < g_kept[b]);
    int anc = on ? g_picks[b * MAXDET + r] : 0;
    size_t g = (size_t)b * NN + anc;
    if (lane < 6) {
        float x = 0.0f;
        if (on) {
            float4 bx = g_cbox[g];
            float2 m  = g_cmeta[g];
            x = (lane == 0) ? bx.x : (lane == 1) ? bx.y : (lane == 2) ? bx.z :
                (lane == 3) ? bx.w : (lane == 4) ? m.x : m.y;
        }
        out[(size_t)row * 6 + lane] = x;
    } else if (lane == 6) {
        out[412800 + row] = on ? 1.0f : 0.0f;
    }
    for (int c = lane; c < NCLS; c += 32) {
        float x = on ? logits[g * NCLS + c] : 0.0f;
        out[28800 + (size_t)row * NCLS + c] = x;
    }
}

// ------------------------------------------------------------------
extern "C" void kernel_launch(void* const* d_in, const int* in_sizes, int n_in,
                              void* d_out, int out_size) {
    (void)in_sizes; (void)n_in; (void)out_size;
    const float* pred   = (const float*)d_in[0];
    const float* logits = (const float*)d_in[1];
    float* out = (float*)d_out;

    const int prep_smem = TILE * ROWW * 4;                         // 43520 B
    const int nms_smem  = CAP * 8 + CAP * 16 + CAP + PAIRCAP * 4
                        + 2 * MASKW * 8;                           // 57600 B
    cudaFuncSetAttribute(k_prep, cudaFuncAttributeMaxDynamicSharedMemorySize, prep_smem);
    cudaFuncSetAttribute(k_nms,  cudaFuncAttributeMaxDynamicSharedMemorySize, nms_smem);

    const int gx = (NN + TILE - 1) / TILE;   // 197
    // prep split 6/5/5 so k_nms is the 4th launch (the one ncu captures)
    k_prep<<<dim3(gx, 6), 256, prep_smem>>>(pred, 0);
    k_prep<<<dim3(gx, 5), 256, prep_smem>>>(pred, 6);
    k_prep<<<dim3(gx, 5), 256, prep_smem>>>(pred, 11);

    k_nms<<<BB, 1024, nms_smem>>>();

    k_out<<<BB * MAXDET / 8, 256>>>(logits, out);
}

// round 12
// speedup vs baseline: 1.1387x; 1.1387x over previous
#include <cuda_runtime.h>

#define BB      16
#define NN      25200
#define NCLS    80
#define ROWW    85
#define NBUCK   1024
#define CAP     1024
#define KSEL    640
#define MAXDET  300
#define MASKW   (CAP / 64)     // 16 u64 words
#define PAIRCAP 8192
#define TILE    128

typedef unsigned long long u64;

// ---- static device scratch (no runtime allocation allowed) ----
__device__ float4 g_cbox[BB * NN];      // xyxy per anchor
__device__ float2 g_cmeta[BB * NN];     // (conf or -1, class as float)
__device__ int    g_hist[BB * NBUCK];   // zero-init; k_thresh restores zeros
__device__ int    g_thresh[BB];
__device__ int    g_selcount[BB];
__device__ u64    g_selkeys[BB * CAP];
__device__ int    g_sanchor[BB * CAP];  // sorted anchor ids
__device__ int    g_M[BB];
__device__ int    g_pairs[BB * PAIRCAP];
__device__ int    g_npairs[BB];
__device__ u64    g_rflag[BB * MASKW];
__device__ int    g_picks[BB * MAXDET];
__device__ int    g_kept[BB];

__device__ __forceinline__ unsigned su32(const void* p) {
    unsigned r;
    asm("{ .reg .u64 t; cvta.to.shared.u64 t, %1; cvt.u32.u64 %0, t; }"
        : "=r"(r) : "l"(p));
    return r;
}

// ------------------------------------------------------------------
// 1) Preprocess: cp.async staging, per-anchor class argmax, box decode,
//    score histogram.
__global__ void __launch_bounds__(256) k_prep(const float* __restrict__ pred) {
    extern __shared__ float psm[];                 // 128*85 floats = 43520 B
    int b  = blockIdx.y;
    int a0 = blockIdx.x * TILE;
    int rows = NN - a0; if (rows > TILE) rows = TILE;   // 128 or 112, both %4==0
    const float4* gp4 = (const float4*)(pred + ((size_t)b * NN + a0) * ROWW);
    int nvec = rows * ROWW / 4;
    unsigned sbase = su32(psm);
    for (int k = threadIdx.x; k < nvec; k += 256) {
        asm volatile("cp.async.cg.shared.global [%0], [%1], 16;"
                     :: "r"(sbase + k * 16), "l"(gp4 + k));
    }
    asm volatile("cp.async.commit_group;");
    asm volatile("cp.async.wait_group 0;" ::: "memory");
    __syncthreads();

    int t = threadIdx.x;
    if (t < rows) {
        const float* p = psm + t * ROWW;
        float cx = p[0], cy = p[1], w = p[2], h = p[3], obj = p[4];
        float best = -1.0f; int bj = 0;
#pragma unroll 8
        for (int c = 0; c < NCLS; c++) {
            float v = __fmul_rn(p[5 + c], obj);   // same rounding as reference
            if (v > best) { best = v; bj = c; }   // first-max tie-break
        }
        float hw = __fmul_rn(w, 0.5f), hh = __fmul_rn(h, 0.5f);
        float4 box = make_float4(__fsub_rn(cx, hw), __fsub_rn(cy, hh),
                                 __fadd_rn(cx, hw), __fadd_rn(cy, hh));
        bool valid = (obj > 0.25f) && (best > 0.25f);
        size_t g = (size_t)b * NN + a0 + t;
        g_cbox[g]  = box;
        g_cmeta[g] = make_float2(valid ? best : -1.0f, (float)bj);
        if (valid) {
            int bkt = (int)(best * 1024.0f);      // *1024 exact (pow2)
            if (bkt > NBUCK - 1) bkt = NBUCK - 1;
            atomicAdd(&g_hist[b * NBUCK + bkt], 1);
        }
    }
}

// ------------------------------------------------------------------
// 2) Per-image cutoff (warp per image), then restore g_hist zeros and
//    reset g_selcount.
__global__ void __launch_bounds__(512) k_thresh() {
    int w = threadIdx.x >> 5, lane = threadIdx.x & 31;
    int b = w;                                  // 16 warps == BB
    int total = 0, thr = 0;
    for (int c = 0; c < 32; c++) {
        int k = 1023 - (c * 32 + lane);
        int s = g_hist[b * NBUCK + k];
#pragma unroll
        for (int off = 1; off < 32; off <<= 1) {
            int u = __shfl_up_sync(0xffffffffu, s, off);
            if (lane >= off) s += u;
        }
        int S = total + s;
        unsigned bal = __ballot_sync(0xffffffffu, S >= KSEL);
        if (bal) {
            int f  = __ffs(bal) - 1;
            int Sf = __shfl_sync(0xffffffffu, S, f);
            int kk = 1023 - (c * 32 + f);
            thr = (Sf > CAP) ? kk + 1 : kk;      // suffix(kk+1) < KSEL <= CAP
            break;
        }
        total = __shfl_sync(0xffffffffu, S, 31);
    }
    if (lane == 0) { g_thresh[b] = thr; g_selcount[b] = 0; }
    for (int c = 0; c < 32; c++)                 // restore zeros for next replay
        g_hist[b * NBUCK + c * 32 + lane] = 0;
}

// ------------------------------------------------------------------
// 3) Chip-wide compaction with block-aggregated global atomics.
__global__ void __launch_bounds__(256) k_compact() {
    __shared__ int wcnt[8], wbase[8], blkbase;
    int b = blockIdx.y;
    int a = blockIdx.x * 256 + threadIdx.x;
    int w = threadIdx.x >> 5, lane = threadIdx.x & 31;
    bool sel = false; u64 key = 0;
    if (a < NN) {
        float2 m = g_cmeta[(size_t)b * NN + a];
        if (m.x > 0.0f) {
            int bkt = (int)(m.x * 1024.0f);
            if (bkt > NBUCK - 1) bkt = NBUCK - 1;
            if (bkt >= g_thresh[b]) {
                sel = true;
                key = ((u64)__float_as_uint(m.x) << 32) | (u64)(~(unsigned)a);
            }
        }
    }
    unsigned ball = __ballot_sync(0xffffffffu, sel);
    if (lane == 0) wcnt[w] = __popc(ball);
    __syncthreads();
    if (threadIdx.x == 0) {
        int tot = 0;
#pragma unroll
        for (int i = 0; i < 8; i++) { wbase[i] = tot; tot += wcnt[i]; }
        blkbase = tot ? atomicAdd(&g_selcount[b], tot) : 0;
    }
    __syncthreads();
    if (sel) {
        int pos = blkbase + wbase[w] + __popc(ball & ((1u << lane) - 1));
        if (pos < CAP) g_selkeys[b * CAP + pos] = key;   // total provably <= CAP
    }
}

// ------------------------------------------------------------------
// Bitonic compare-exchange via shfl (element per thread), desc final order.
__device__ __forceinline__ u64 casx(u64 v, int j, int k, int t) {
    u64 o = __shfl_xor_sync(0xffffffffu, v, j);
    bool takemax = (((t & j) == 0) == ((t & k) == 0));
    return takemax ? (v > o ? v : o) : (v < o ? v : o);
}

// ------------------------------------------------------------------
// 4) Sort + offset-box build + sparse pairwise suppression mask.
//    (launch slot 4 -> this is the kernel ncu captures)
__global__ void __launch_bounds__(1024, 1) k_sortmask() {
    extern __shared__ char dynsm[];
    u64*           keys   = (u64*)dynsm;                                  // 8KB
    float4*        obox   = (float4*)(dynsm + CAP * 8);                   // 16KB
    unsigned char* cls    = (unsigned char*)(dynsm + CAP * 8 + CAP * 16); // 1KB
    int*           pairs  = (int*)(dynsm + CAP * 8 + CAP * 16 + CAP);     // 32KB
    u64*           rflagw = (u64*)((char*)pairs + PAIRCAP * 4);           // 128B
    __shared__ int s_np;

    int b = blockIdx.x, t = threadIdx.x;
    if (t == 0) s_np = 0;
    if (t < MASKW) rflagw[t] = 0ULL;
    int M = g_selcount[b]; if (M > CAP) M = CAP;
    keys[t] = (t < M) ? g_selkeys[b * CAP + t] : 0ULL;
    __syncthreads();

    // --- hybrid bitonic sort: shfl for j<32, SMEM+barrier for j>=32
    {
        u64 v = keys[t];
#pragma unroll
        for (int k = 2; k <= 32; k <<= 1)
#pragma unroll
            for (int j = k >> 1; j >= 1; j >>= 1)
                v = casx(v, j, k, t);
        for (int k = 64; k <= CAP; k <<= 1) {
            keys[t] = v;
            __syncthreads();
            for (int j = k >> 1; j >= 32; j >>= 1) {
                int i = t, l = i ^ j;
                if (l > i) {
                    u64 x = keys[i], y = keys[l];
                    if ((x < y) == ((i & k) == 0)) { keys[i] = y; keys[l] = x; }
                }
                __syncthreads();
            }
            v = keys[t];
#pragma unroll
            for (int j = 16; j >= 1; j >>= 1)
                v = casx(v, j, k, t);
        }
        keys[t] = v;
    }
    __syncthreads();

    // --- build sorted anchors / offset boxes / class
    if (t < M) {
        unsigned anc = ~(unsigned)(keys[t] & 0xFFFFFFFFULL);
        size_t g = (size_t)b * NN + anc;
        float4 bx = g_cbox[g];
        float  jf = g_cmeta[g].y;
        float off = jf * 4096.0f;   // exact
        obox[t] = make_float4(__fadd_rn(bx.x, off), __fadd_rn(bx.y, off),
                              __fadd_rn(bx.z, off), __fadd_rn(bx.w, off));
        cls[t] = (unsigned char)(int)jf;
        g_sanchor[b * CAP + t] = (int)anc;
    }
    __syncthreads();

    // --- sparse pairwise suppression: thread i scans j>i of same class;
    //     IoU>0.45 pairs appended to SMEM list; rflag bit set for row i.
#define CHECKJ(jj) do { \
        float4 bj = obox[jj]; \
        float ltx = fmaxf(bi.x, bj.x), lty = fmaxf(bi.y, bj.y); \
        float rbx = fminf(bi.z, bj.z), rby = fminf(bi.w, bj.w); \
        float ww = fmaxf(__fsub_rn(rbx, ltx), 0.0f); \
        float hh = fmaxf(__fsub_rn(rby, lty), 0.0f); \
        float inter = __fmul_rn(ww, hh); \
        float a2 = __fmul_rn(__fsub_rn(bj.z, bj.x), __fsub_rn(bj.w, bj.y)); \
        float den = __fadd_rn(__fsub_rn(__fadd_rn(a1, a2), inter), 1e-9f); \
        if (__fdiv_rn(inter, den) > 0.45f) { \
            int p = atomicAdd(&s_np, 1); \
            if (p < PAIRCAP) pairs[p] = (i << 10) | (jj); \
            any = 1; \
        } \
    } while (0)

    if (t < M) {
        int i = t;
        unsigned char ci = cls[i];
        float4 bi = obox[i];
        float a1 = __fmul_rn(__fsub_rn(bi.z, bi.x), __fsub_rn(bi.w, bi.y));
        unsigned cw = (unsigned)ci * 0x01010101u;
        int any = 0;
        int j = i + 1;
        while (j < M && (j & 3)) { if (cls[j] == ci) CHECKJ(j); j++; }
        const unsigned* c32 = (const unsigned*)cls;
        for (; j + 4 <= M; j += 4) {
            unsigned w4 = c32[j >> 2];
            unsigned eq = __vcmpeq4(w4, cw);
            if (eq) {
                if (eq & 0x000000ffu) CHECKJ(j);
                if (eq & 0x0000ff00u) CHECKJ(j + 1);
                if (eq & 0x00ff0000u) CHECKJ(j + 2);
                if (eq & 0xff000000u) CHECKJ(j + 3);
            }
        }
        while (j < M) { if (cls[j] == ci) CHECKJ(j); j++; }
        if (any) atomicOr(rflagw + (i >> 6), 1ULL << (i & 63));
    }
#undef CHECKJ
    __syncthreads();

    // --- flush to global
    int np = s_np; if (np > PAIRCAP) np = PAIRCAP;
    for (int e = t; e < np; e += 1024) g_pairs[b * PAIRCAP + e] = pairs[e];
    if (t < MASKW) g_rflag[b * MASKW + t] = rflagw[t];
    if (t == 0) { g_npairs[b] = np; g_M[b] = M; }
}

// ------------------------------------------------------------------
// n-th (0-indexed) set bit of a 64-bit mask
__device__ __forceinline__ int sel64(u64 m, int n) {
    unsigned lo = (unsigned)m, hi = (unsigned)(m >> 32);
    int c = __popc(lo);
    return (n < c) ? (int)__fns(lo, 0, n + 1) : 32 + (int)__fns(hi, 0, n - c + 1);
}

// ------------------------------------------------------------------
// 5) Warp-per-image greedy scan with optimistic 64-candidate batching.
__global__ void __launch_bounds__(32) k_scan() {
    __shared__ u64 rem[MASKW];
    int b = blockIdx.x, lane = threadIdx.x;
    if (lane < MASKW) rem[lane] = 0ULL;
    __syncwarp();

    int M = g_M[b];
    int P = g_npairs[b];
    int nk = 0;
    for (int c = 0; c * 64 < M && nk < MAXDET; c++) {
        int base = c * 64;
        int lim = M - base; if (lim > 64) lim = 64;
        u64 limmask = (lim == 64) ? ~0ULL : ((1ULL << lim) - 1);
        u64 rfl   = g_rflag[b * MASKW + c];
        u64 alive = ~rem[c] & limmask;
        while (alive && nk < MAXDET) {
            u64 fa = alive & rfl;
            if (!fa) {
                // no suppressor in this word: emit every alive bit in order
                int cnt  = __popcll(alive);
                int take = MAXDET - nk; if (take > cnt) take = cnt;
                for (int s = lane; s < take; s += 32) {
                    int pos = sel64(alive, s);
                    g_picks[b * MAXDET + nk + s] = g_sanchor[b * CAP + base + pos];
                }
                nk += take;
                alive = 0ULL;
            } else {
                int f = __ffsll(fa) - 1;
                u64 pre = alive & ((1ULL << f) - 1);    // alive bits before f (none flagged)
                int cnt  = __popcll(pre);
                int take = MAXDET - nk; if (take > cnt) take = cnt;
                for (int s = lane; s < take; s += 32) {
                    int pos = sel64(pre, s);
                    g_picks[b * MAXDET + nk + s] = g_sanchor[b * CAP + base + pos];
                }
                nk += take;
                if (nk < MAXDET) {
                    if (lane == 0)
                        g_picks[b * MAXDET + nk] = g_sanchor[b * CAP + base + f];
                    nk++;
                    int i = base + f;
                    for (int e = lane; e < P; e += 32) {    // apply i's suppressions
                        int pr = g_pairs[b * PAIRCAP + e];
                        if ((pr >> 10) == i) {
                            int jj = pr & 1023;
                            atomicOr(&rem[jj >> 6], 1ULL << (jj & 63));
                        }
                    }
                    __syncwarp();
                    alive &= ~((2ULL << f) - 1);   // drop bits <= f (f=63: 2<<63==0 -> alive=0)
                    alive &= ~rem[c] & limmask;    // refresh current word
                } else {
                    alive = 0ULL;
                }
            }
        }
    }
    if (lane == 0) g_kept[b] = nk;
}

// ------------------------------------------------------------------
// 6) Output: [dets (B,300,6)] [lg (B,300,80)] [keep (B,300)] as float32.
__global__ void __launch_bounds__(256) k_out(const float* __restrict__ logits,
                                             float* __restrict__ out) {
    int row  = blockIdx.x * 8 + (threadIdx.x >> 5);   // 0..4799
    int lane = threadIdx.x & 31;
    int b = row / MAXDET, r = row % MAXDET;
    bool on = (r < g_kept[b]);
    int anc = on ? g_picks[b * MAXDET + r] : 0;
    size_t g = (size_t)b * NN + anc;
    if (lane < 6) {
        float x = 0.0f;
        if (on) {
            float4 bx = g_cbox[g];
            float2 m  = g_cmeta[g];
            x = (lane == 0) ? bx.x : (lane == 1) ? bx.y : (lane == 2) ? bx.z :
                (lane == 3) ? bx.w : (lane == 4) ? m.x : m.y;
        }
        out[(size_t)row * 6 + lane] = x;
    } else if (lane == 6) {
        out[412800 + row] = on ? 1.0f : 0.0f;
    }
    for (int c = lane; c < NCLS; c += 32) {
        float x = on ? logits[g * NCLS + c] : 0.0f;
        out[28800 + (size_t)row * NCLS + c] = x;
    }
}

// ------------------------------------------------------------------
extern "C" void kernel_launch(void* const* d_in, const int* in_sizes, int n_in,
                              void* d_out, int out_size) {
    (void)in_sizes; (void)n_in; (void)out_size;
    const float* pred   = (const float*)d_in[0];
    const float* logits = (const float*)d_in[1];
    float* out = (float*)d_out;

    const int prep_smem = TILE * ROWW * 4;                           // 43520 B
    const int sm_smem   = CAP * 8 + CAP * 16 + CAP + PAIRCAP * 4
                        + MASKW * 8;                                 // 58496 B
    cudaFuncSetAttribute(k_prep,     cudaFuncAttributeMaxDynamicSharedMemorySize, prep_smem);
    cudaFuncSetAttribute(k_sortmask, cudaFuncAttributeMaxDynamicSharedMemorySize, sm_smem);

    k_prep<<<dim3((NN + TILE - 1) / TILE, BB), 256, prep_smem>>>(pred);   // 1
    k_thresh<<<1, 512>>>();                                               // 2
    k_compact<<<dim3((NN + 255) / 256, BB), 256>>>();                     // 3
    k_sortmask<<<BB, 1024, sm_smem>>>();                                  // 4 <- ncu
    k_scan<<<BB, 32>>>();                                                 // 5
    k_out<<<BB * MAXDET / 8, 256>>>(logits, out);                         // 6
}

// round 13
// speedup vs baseline: 2.2878x; 2.0092x over previous
#include <cuda_runtime.h>

#define BB      16
#define NN      25200
#define NCLS    80
#define ROWW    85
#define NBUCK   1024
#define CAP     1024
#define KSEL    640
#define MAXDET  300
#define MASKW   (CAP / 64)     // 16 u64 words
#define PAIRCAP 8192
#define TILE    128

typedef unsigned long long u64;

// ---- static device scratch (no runtime allocation allowed) ----
__device__ float4 g_cbox[BB * NN];      // xyxy per anchor
__device__ float2 g_cmeta[BB * NN];     // (conf or -1, class as float)
__device__ int    g_hist[BB * NBUCK];   // zero-init; k_thresh restores zeros
__device__ int    g_thresh[BB];
__device__ int    g_selcount[BB];
__device__ u64    g_selkeys[BB * CAP];
__device__ int    g_sanchor[BB * CAP];  // sorted anchor ids
__device__ int    g_M[BB];
__device__ int    g_pairs[BB * PAIRCAP];
__device__ int    g_npairs[BB];
__device__ u64    g_rflag[BB * MASKW];
__device__ int    g_picks[BB * MAXDET];
__device__ int    g_kept[BB];

__device__ __forceinline__ unsigned su32(const void* p) {
    unsigned r;
    asm("{ .reg .u64 t; cvta.to.shared.u64 t, %1; cvt.u32.u64 %0, t; }"
        : "=r"(r) : "l"(p));
    return r;
}

// ------------------------------------------------------------------
// 1) Preprocess: cp.async staging, per-anchor class argmax, box decode,
//    score histogram.
__global__ void __launch_bounds__(256) k_prep(const float* __restrict__ pred) {
    extern __shared__ float psm[];                 // 128*85 floats = 43520 B
    int b  = blockIdx.y;
    int a0 = blockIdx.x * TILE;
    int rows = NN - a0; if (rows > TILE) rows = TILE;   // 128 or 112, both %4==0
    const float4* gp4 = (const float4*)(pred + ((size_t)b * NN + a0) * ROWW);
    int nvec = rows * ROWW / 4;
    unsigned sbase = su32(psm);
    for (int k = threadIdx.x; k < nvec; k += 256) {
        asm volatile("cp.async.cg.shared.global [%0], [%1], 16;"
                     :: "r"(sbase + k * 16), "l"(gp4 + k));
    }
    asm volatile("cp.async.commit_group;");
    asm volatile("cp.async.wait_group 0;" ::: "memory");
    __syncthreads();

    int t = threadIdx.x;
    if (t < rows) {
        const float* p = psm + t * ROWW;
        float cx = p[0], cy = p[1], w = p[2], h = p[3], obj = p[4];
        float best = -1.0f; int bj = 0;
#pragma unroll 8
        for (int c = 0; c < NCLS; c++) {
            float v = __fmul_rn(p[5 + c], obj);   // same rounding as reference
            if (v > best) { best = v; bj = c; }   // first-max tie-break
        }
        float hw = __fmul_rn(w, 0.5f), hh = __fmul_rn(h, 0.5f);
        float4 box = make_float4(__fsub_rn(cx, hw), __fsub_rn(cy, hh),
                                 __fadd_rn(cx, hw), __fadd_rn(cy, hh));
        bool valid = (obj > 0.25f) && (best > 0.25f);
        size_t g = (size_t)b * NN + a0 + t;
        g_cbox[g]  = box;
        g_cmeta[g] = make_float2(valid ? best : -1.0f, (float)bj);
        if (valid) {
            int bkt = (int)(best * 1024.0f);      // *1024 exact (pow2)
            if (bkt > NBUCK - 1) bkt = NBUCK - 1;
            atomicAdd(&g_hist[b * NBUCK + bkt], 1);
        }
    }
}

// ------------------------------------------------------------------
// 2) Per-image cutoff (warp per image), then restore g_hist zeros and
//    reset g_selcount.
__global__ void __launch_bounds__(512) k_thresh() {
    int w = threadIdx.x >> 5, lane = threadIdx.x & 31;
    int b = w;                                  // 16 warps == BB
    int total = 0, thr = 0;
    for (int c = 0; c < 32; c++) {
        int k = 1023 - (c * 32 + lane);
        int s = g_hist[b * NBUCK + k];
#pragma unroll
        for (int off = 1; off < 32; off <<= 1) {
            int u = __shfl_up_sync(0xffffffffu, s, off);
            if (lane >= off) s += u;
        }
        int S = total + s;
        unsigned bal = __ballot_sync(0xffffffffu, S >= KSEL);
        if (bal) {
            int f  = __ffs(bal) - 1;
            int Sf = __shfl_sync(0xffffffffu, S, f);
            int kk = 1023 - (c * 32 + f);
            thr = (Sf > CAP) ? kk + 1 : kk;      // suffix(kk+1) < KSEL <= CAP
            break;
        }
        total = __shfl_sync(0xffffffffu, S, 31);
    }
    if (lane == 0) { g_thresh[b] = thr; g_selcount[b] = 0; }
    for (int c = 0; c < 32; c++)                 // restore zeros for next replay
        g_hist[b * NBUCK + c * 32 + lane] = 0;
}

// ------------------------------------------------------------------
// 3) Chip-wide compaction with block-aggregated global atomics.
__global__ void __launch_bounds__(256) k_compact() {
    __shared__ int wcnt[8], wbase[8], blkbase;
    int b = blockIdx.y;
    int a = blockIdx.x * 256 + threadIdx.x;
    int w = threadIdx.x >> 5, lane = threadIdx.x & 31;
    bool sel = false; u64 key = 0;
    if (a < NN) {
        float2 m = g_cmeta[(size_t)b * NN + a];
        if (m.x > 0.0f) {
            int bkt = (int)(m.x * 1024.0f);
            if (bkt > NBUCK - 1) bkt = NBUCK - 1;
            if (bkt >= g_thresh[b]) {
                sel = true;
                key = ((u64)__float_as_uint(m.x) << 32) | (u64)(~(unsigned)a);
            }
        }
    }
    unsigned ball = __ballot_sync(0xffffffffu, sel);
    if (lane == 0) wcnt[w] = __popc(ball);
    __syncthreads();
    if (threadIdx.x == 0) {
        int tot = 0;
#pragma unroll
        for (int i = 0; i < 8; i++) { wbase[i] = tot; tot += wcnt[i]; }
        blkbase = tot ? atomicAdd(&g_selcount[b], tot) : 0;
    }
    __syncthreads();
    if (sel) {
        int pos = blkbase + wbase[w] + __popc(ball & ((1u << lane) - 1));
        if (pos < CAP) g_selkeys[b * CAP + pos] = key;   // total provably <= CAP
    }
}

// ------------------------------------------------------------------
// Bitonic compare-exchange via shfl (element per thread), desc final order.
__device__ __forceinline__ u64 casx(u64 v, int j, int k, int t) {
    u64 o = __shfl_xor_sync(0xffffffffu, v, j);
    bool takemax = (((t & j) == 0) == ((t & k) == 0));
    return takemax ? (v > o ? v : o) : (v < o ? v : o);
}

// ------------------------------------------------------------------
// 4) Sort + offset-box build + CLASS-SEGMENTED pairwise suppression mask.
//    (launch slot 4 -> this is the kernel ncu captures)
__global__ void __launch_bounds__(1024, 1) k_sortmask() {
    extern __shared__ char dynsm[];
    u64*           keys    = (u64*)dynsm;                                  // 8KB
    float4*        obox    = (float4*)(dynsm + CAP * 8);                   // 16KB
    unsigned char* cls     = (unsigned char*)(dynsm + CAP * 8 + CAP * 16); // 1KB
    int*           byclass = (int*)(dynsm + CAP * 8 + CAP * 16 + CAP);     // 4KB
    int*           pairs   = (int*)((char*)byclass + CAP * 4);             // 32KB
    u64*           rflagw  = (u64*)((char*)pairs + PAIRCAP * 4);           // 128B
    __shared__ int s_np;
    __shared__ int ccount[NCLS], cbase[NCLS], cofs[NCLS];

    int b = blockIdx.x, t = threadIdx.x;
    if (t == 0) s_np = 0;
    if (t < MASKW) rflagw[t] = 0ULL;
    if (t < NCLS) { ccount[t] = 0; cofs[t] = 0; }
    int M = g_selcount[b]; if (M > CAP) M = CAP;
    keys[t] = (t < M) ? g_selkeys[b * CAP + t] : 0ULL;
    __syncthreads();

    // --- hybrid bitonic sort: shfl for j<32, SMEM+barrier for j>=32
    {
        u64 v = keys[t];
#pragma unroll
        for (int k = 2; k <= 32; k <<= 1)
#pragma unroll
            for (int j = k >> 1; j >= 1; j >>= 1)
                v = casx(v, j, k, t);
        for (int k = 64; k <= CAP; k <<= 1) {
            keys[t] = v;
            __syncthreads();
            for (int j = k >> 1; j >= 32; j >>= 1) {
                int i = t, l = i ^ j;
                if (l > i) {
                    u64 x = keys[i], y = keys[l];
                    if ((x < y) == ((i & k) == 0)) { keys[i] = y; keys[l] = x; }
                }
                __syncthreads();
            }
            v = keys[t];
#pragma unroll
            for (int j = 16; j >= 1; j >>= 1)
                v = casx(v, j, k, t);
        }
        keys[t] = v;
    }
    __syncthreads();

    // --- build sorted anchors / offset boxes / class; count classes
    int myc = -1;
    if (t < M) {
        unsigned anc = ~(unsigned)(keys[t] & 0xFFFFFFFFULL);
        size_t g = (size_t)b * NN + anc;
        float4 bx = g_cbox[g];
        float  jf = g_cmeta[g].y;
        float off = jf * 4096.0f;   // exact
        obox[t] = make_float4(__fadd_rn(bx.x, off), __fadd_rn(bx.y, off),
                              __fadd_rn(bx.z, off), __fadd_rn(bx.w, off));
        myc = (int)jf;
        cls[t] = (unsigned char)myc;
        g_sanchor[b * CAP + t] = (int)anc;
        atomicAdd(&ccount[myc], 1);
    }
    __syncthreads();

    // --- serial prefix over 80 classes (cheap), then scatter ranks into
    //     class segments (order within segment irrelevant)
    if (t == 0) {
        int s = 0;
        for (int c = 0; c < NCLS; c++) { cbase[c] = s; s += ccount[c]; }
    }
    __syncthreads();
    if (t < M) byclass[cbase[myc] + atomicAdd(&cofs[myc], 1)] = t;
    __syncthreads();

    // --- class-segmented pairwise suppression: thread t (rank t) scans its
    //     own class segment; records pair (t, rj) once for each rj > t with
    //     IoU(offset boxes) > 0.45. Every lane does useful IoU work.
    if (t < M) {
        int s0 = cbase[myc], L = ccount[myc];
        float4 bi = obox[t];
        float a1 = __fmul_rn(__fsub_rn(bi.z, bi.x), __fsub_rn(bi.w, bi.y));
        int any = 0;
        for (int p = 0; p < L; p++) {
            int rj = byclass[s0 + p];
            if (rj > t) {
                float4 bj = obox[rj];
                float ltx = fmaxf(bi.x, bj.x), lty = fmaxf(bi.y, bj.y);
                float rbx = fminf(bi.z, bj.z), rby = fminf(bi.w, bj.w);
                float ww = fmaxf(__fsub_rn(rbx, ltx), 0.0f);
                float hh = fmaxf(__fsub_rn(rby, lty), 0.0f);
                float inter = __fmul_rn(ww, hh);
                float a2 = __fmul_rn(__fsub_rn(bj.z, bj.x), __fsub_rn(bj.w, bj.y));
                float den = __fadd_rn(__fsub_rn(__fadd_rn(a1, a2), inter), 1e-9f);
                if (__fdiv_rn(inter, den) > 0.45f) {
                    int p2 = atomicAdd(&s_np, 1);
                    if (p2 < PAIRCAP) pairs[p2] = (t << 10) | rj;
                    any = 1;
                }
            }
        }
        if (any) atomicOr(rflagw + (t >> 6), 1ULL << (t & 63));
    }
    __syncthreads();

    // --- flush to global
    int np = s_np; if (np > PAIRCAP) np = PAIRCAP;
    for (int e = t; e < np; e += 1024) g_pairs[b * PAIRCAP + e] = pairs[e];
    if (t < MASKW) g_rflag[b * MASKW + t] = rflagw[t];
    if (t == 0) { g_npairs[b] = np; g_M[b] = M; }
}

// ------------------------------------------------------------------
// n-th (0-indexed) set bit of a 64-bit mask
__device__ __forceinline__ int sel64(u64 m, int n) {
    unsigned lo = (unsigned)m, hi = (unsigned)(m >> 32);
    int c = __popc(lo);
    return (n < c) ? (int)__fns(lo, 0, n + 1) : 32 + (int)__fns(hi, 0, n - c + 1);
}

// ------------------------------------------------------------------
// 5) Warp-per-image greedy scan with optimistic 64-candidate batching.
__global__ void __launch_bounds__(32) k_scan() {
    __shared__ u64 rem[MASKW];
    int b = blockIdx.x, lane = threadIdx.x;
    if (lane < MASKW) rem[lane] = 0ULL;
    __syncwarp();

    int M = g_M[b];
    int P = g_npairs[b];
    int nk = 0;
    for (int c = 0; c * 64 < M && nk < MAXDET; c++) {
        int base = c * 64;
        int lim = M - base; if (lim > 64) lim = 64;
        u64 limmask = (lim == 64) ? ~0ULL : ((1ULL << lim) - 1);
        u64 rfl   = g_rflag[b * MASKW + c];
        u64 alive = ~rem[c] & limmask;
        while (alive && nk < MAXDET) {
            u64 fa = alive & rfl;
            if (!fa) {
                int cnt  = __popcll(alive);
                int take = MAXDET - nk; if (take > cnt) take = cnt;
                for (int s = lane; s < take; s += 32) {
                    int pos = sel64(alive, s);
                    g_picks[b * MAXDET + nk + s] = g_sanchor[b * CAP + base + pos];
                }
                nk += take;
                alive = 0ULL;
            } else {
                int f = __ffsll(fa) - 1;
                u64 pre = alive & ((1ULL << f) - 1);
                int cnt  = __popcll(pre);
                int take = MAXDET - nk; if (take > cnt) take = cnt;
                for (int s = lane; s < take; s += 32) {
                    int pos = sel64(pre, s);
                    g_picks[b * MAXDET + nk + s] = g_sanchor[b * CAP + base + pos];
                }
                nk += take;
                if (nk < MAXDET) {
                    if (lane == 0)
                        g_picks[b * MAXDET + nk] = g_sanchor[b * CAP + base + f];
                    nk++;
                    int i = base + f;
                    for (int e = lane; e < P; e += 32) {
                        int pr = g_pairs[b * PAIRCAP + e];
                        if ((pr >> 10) == i) {
                            int jj = pr & 1023;
                            atomicOr(&rem[jj >> 6], 1ULL << (jj & 63));
                        }
                    }
                    __syncwarp();
                    alive &= ~((2ULL << f) - 1);
                    alive &= ~rem[c] & limmask;
                } else {
                    alive = 0ULL;
                }
            }
        }
    }
    if (lane == 0) g_kept[b] = nk;
}

// ------------------------------------------------------------------
// 6) Output: [dets (B,300,6)] [lg (B,300,80)] [keep (B,300)] as float32.
__global__ void __launch_bounds__(256) k_out(const float* __restrict__ logits,
                                             float* __restrict__ out) {
    int row  = blockIdx.x * 8 + (threadIdx.x >> 5);   // 0..4799
    int lane = threadIdx.x & 31;
    int b = row / MAXDET, r = row % MAXDET;
    bool on = (r < g_kept[b]);
    int anc = on ? g_picks[b * MAXDET + r] : 0;
    size_t g = (size_t)b * NN + anc;
    if (lane < 6) {
        float x = 0.0f;
        if (on) {
            float4 bx = g_cbox[g];
            float2 m  = g_cmeta[g];
            x = (lane == 0) ? bx.x : (lane == 1) ? bx.y : (lane == 2) ? bx.z :
                (lane == 3) ? bx.w : (lane == 4) ? m.x : m.y;
        }
        out[(size_t)row * 6 + lane] = x;
    } else if (lane == 6) {
        out[412800 + row] = on ? 1.0f : 0.0f;
    }
    for (int c = lane; c < NCLS; c += 32) {
        float x = on ? logits[g * NCLS + c] : 0.0f;
        out[28800 + (size_t)row * NCLS + c] = x;
    }
}

// ------------------------------------------------------------------
extern "C" void kernel_launch(void* const* d_in, const int* in_sizes, int n_in,
                              void* d_out, int out_size) {
    (void)in_sizes; (void)n_in; (void)out_size;
    const float* pred   = (const float*)d_in[0];
    const float* logits = (const float*)d_in[1];
    float* out = (float*)d_out;

    const int prep_smem = TILE * ROWW * 4;                           // 43520 B
    const int sm_smem   = CAP * 8 + CAP * 16 + CAP + CAP * 4
                        + PAIRCAP * 4 + MASKW * 8;                   // 62592 B
    cudaFuncSetAttribute(k_prep,     cudaFuncAttributeMaxDynamicSharedMemorySize, prep_smem);
    cudaFuncSetAttribute(k_sortmask, cudaFuncAttributeMaxDynamicSharedMemorySize, sm_smem);

    k_prep<<<dim3((NN + TILE - 1) / TILE, BB), 256, prep_smem>>>(pred);   // 1
    k_thresh<<<1, 512>>>();                                               // 2
    k_compact<<<dim3((NN + 255) / 256, BB), 256>>>();                     // 3
    k_sortmask<<<BB, 1024, sm_smem>>>();                                  // 4 <- ncu
    k_scan<<<BB, 32>>>();                                                 // 5
    k_out<<<BB * MAXDET / 8, 256>>>(logits, out);                         // 6
}

// round 16
// speedup vs baseline: 2.5310x; 1.1063x over previous
#include <cuda_runtime.h>

#define BB      16
#define NN      25200
#define NCLS    80
#define ROWW    85
#define NBUCK   1024
#define CAP     512
#define KSEL    448
#define MAXDET  300
#define MASKW   (CAP / 64)     // 8 u64 words
#define PAIRCAP 4096
#define TILE    128

typedef unsigned long long u64;

// ---- static device scratch (no runtime allocation allowed) ----
__device__ float4 g_cbox[BB * NN];      // xyxy per anchor
__device__ float2 g_cmeta[BB * NN];     // (conf or -1, class as float)
__device__ int    g_hist[BB * NBUCK];   // zero-init; k_thresh restores zeros
__device__ int    g_thresh[BB];
__device__ int    g_selcount[BB];
__device__ u64    g_selkeys[BB * CAP];
__device__ int    g_picks[BB * MAXDET];
__device__ int    g_kept[BB];

__device__ __forceinline__ unsigned su32(const void* p) {
    unsigned r;
    asm("{ .reg .u64 t; cvta.to.shared.u64 t, %1; cvt.u32.u64 %0, t; }"
        : "=r"(r) : "l"(p));
    return r;
}

// ------------------------------------------------------------------
// 1) Preprocess: cp.async staging, per-anchor class argmax, box decode,
//    score histogram.
__global__ void __launch_bounds__(256) k_prep(const float* __restrict__ pred) {
    extern __shared__ float psm[];                 // 128*85 floats = 43520 B
    int b  = blockIdx.y;
    int a0 = blockIdx.x * TILE;
    int rows = NN - a0; if (rows > TILE) rows = TILE;   // 128 or 112, both %4==0
    const float4* gp4 = (const float4*)(pred + ((size_t)b * NN + a0) * ROWW);
    int nvec = rows * ROWW / 4;
    unsigned sbase = su32(psm);
    for (int k = threadIdx.x; k < nvec; k += 256) {
        asm volatile("cp.async.cg.shared.global [%0], [%1], 16;"
                     :: "r"(sbase + k * 16), "l"(gp4 + k));
    }
    asm volatile("cp.async.commit_group;");
    asm volatile("cp.async.wait_group 0;" ::: "memory");
    __syncthreads();

    int t = threadIdx.x;
    if (t < rows) {
        const float* p = psm + t * ROWW;
        float cx = p[0], cy = p[1], w = p[2], h = p[3], obj = p[4];
        float best = -1.0f; int bj = 0;
#pragma unroll 8
        for (int c = 0; c < NCLS; c++) {
            float v = __fmul_rn(p[5 + c], obj);   // same rounding as reference
            if (v > best) { best = v; bj = c; }   // first-max tie-break
        }
        float hw = __fmul_rn(w, 0.5f), hh = __fmul_rn(h, 0.5f);
        float4 box = make_float4(__fsub_rn(cx, hw), __fsub_rn(cy, hh),
                                 __fadd_rn(cx, hw), __fadd_rn(cy, hh));
        bool valid = (obj > 0.25f) && (best > 0.25f);
        size_t g = (size_t)b * NN + a0 + t;
        g_cbox[g]  = box;
        g_cmeta[g] = make_float2(valid ? best : -1.0f, (float)bj);
        if (valid) {
            int bkt = (int)(best * 1024.0f);      // *1024 exact (pow2)
            if (bkt > NBUCK - 1) bkt = NBUCK - 1;
            atomicAdd(&g_hist[b * NBUCK + bkt], 1);
        }
    }
}

// ------------------------------------------------------------------
// 2) Per-image cutoff (warp per image), then restore g_hist zeros and
//    reset g_selcount.
__global__ void __launch_bounds__(512) k_thresh() {
    int w = threadIdx.x >> 5, lane = threadIdx.x & 31;
    int b = w;                                  // 16 warps == BB
    int total = 0, thr = 0;
    for (int c = 0; c < 32; c++) {
        int k = 1023 - (c * 32 + lane);
        int s = g_hist[b * NBUCK + k];
#pragma unroll
        for (int off = 1; off < 32; off <<= 1) {
            int u = __shfl_up_sync(0xffffffffu, s, off);
            if (lane >= off) s += u;
        }
        int S = total + s;
        unsigned bal = __ballot_sync(0xffffffffu, S >= KSEL);
        if (bal) {
            int f  = __ffs(bal) - 1;
            int Sf = __shfl_sync(0xffffffffu, S, f);
            int kk = 1023 - (c * 32 + f);
            thr = (Sf > CAP) ? kk + 1 : kk;      // suffix(kk+1) < KSEL <= CAP
            break;
        }
        total = __shfl_sync(0xffffffffu, S, 31);
    }
    if (lane == 0) { g_thresh[b] = thr; g_selcount[b] = 0; }
    for (int c = 0; c < 32; c++)                 // restore zeros for next replay
        g_hist[b * NBUCK + c * 32 + lane] = 0;
}

// ------------------------------------------------------------------
// 3) Chip-wide compaction with block-aggregated global atomics.
__global__ void __launch_bounds__(256) k_compact() {
    __shared__ int wcnt[8], wbase[8], blkbase;
    int b = blockIdx.y;
    int a = blockIdx.x * 256 + threadIdx.x;
    int w = threadIdx.x >> 5, lane = threadIdx.x & 31;
    bool sel = false; u64 key = 0;
    if (a < NN) {
        float2 m = g_cmeta[(size_t)b * NN + a];
        if (m.x > 0.0f) {
            int bkt = (int)(m.x * 1024.0f);
            if (bkt > NBUCK - 1) bkt = NBUCK - 1;
            if (bkt >= g_thresh[b]) {
                sel = true;
                key = ((u64)__float_as_uint(m.x) << 32) | (u64)(~(unsigned)a);
            }
        }
    }
    unsigned ball = __ballot_sync(0xffffffffu, sel);
    if (lane == 0) wcnt[w] = __popc(ball);
    __syncthreads();
    if (threadIdx.x == 0) {
        int tot = 0;
#pragma unroll
        for (int i = 0; i < 8; i++) { wbase[i] = tot; tot += wcnt[i]; }
        blkbase = tot ? atomicAdd(&g_selcount[b], tot) : 0;
    }
    __syncthreads();
    if (sel) {
        int pos = blkbase + wbase[w] + __popc(ball & ((1u << lane) - 1));
        if (pos < CAP) g_selkeys[b * CAP + pos] = key;   // total provably <= CAP
    }
}

// ------------------------------------------------------------------
// Bitonic compare-exchange via shfl (element per thread), desc final order.
__device__ __forceinline__ u64 casx(u64 v, int j, int k, int t) {
    u64 o = __shfl_xor_sync(0xffffffffu, v, j);
    bool takemax = (((t & j) == 0) == ((t & k) == 0));
    return takemax ? (v > o ? v : o) : (v < o ? v : o);
}

// n-th (0-indexed) set bit of a 64-bit mask
__device__ __forceinline__ int sel64(u64 m, int n) {
    unsigned lo = (unsigned)m, hi = (unsigned)(m >> 32);
    int c = __popc(lo);
    return (n < c) ? (int)__fns(lo, 0, n + 1) : 32 + (int)__fns(hi, 0, n - c + 1);
}

// ------------------------------------------------------------------
// 4) Fused: sort (512 keys) + offset-box build + class-segmented pairwise
//    suppression + warp-0 greedy bitset scan. (launch slot 4 -> ncu capture)
__global__ void __launch_bounds__(CAP, 1) k_sortmask() {
    extern __shared__ char dynsm[];
    u64*           keys    = (u64*)dynsm;                                  // 4KB
    float4*        obox    = (float4*)(dynsm + CAP * 8);                   // 8KB
    int*           byclass = (int*)(dynsm + CAP * 8 + CAP * 16);           // 2KB
    int*           sanchor = byclass + CAP;                                // 2KB
    int*           pairs   = sanchor + CAP;                                // 16KB
    unsigned char* cls     = (unsigned char*)(pairs + PAIRCAP);            // 512B
    u64*           rflagw  = (u64*)(cls + CAP);                            // 64B
    __shared__ int s_np;
    __shared__ int ccount[NCLS], cbase[NCLS], cofs[NCLS];

    int b = blockIdx.x, t = threadIdx.x;
    if (t == 0) s_np = 0;
    if (t < MASKW) rflagw[t] = 0ULL;
    if (t < NCLS) { ccount[t] = 0; cofs[t] = 0; }
    int M = g_selcount[b]; if (M > CAP) M = CAP;
    keys[t] = (t < M) ? g_selkeys[b * CAP + t] : 0ULL;
    __syncthreads();

    // --- hybrid bitonic sort (desc): shfl for j<32, SMEM+barrier for j>=32
    {
        u64 v = keys[t];
#pragma unroll
        for (int k = 2; k <= 32; k <<= 1)
#pragma unroll
            for (int j = k >> 1; j >= 1; j >>= 1)
                v = casx(v, j, k, t);
        for (int k = 64; k <= CAP; k <<= 1) {
            keys[t] = v;
            __syncthreads();
            for (int j = k >> 1; j >= 32; j >>= 1) {
                int i = t, l = i ^ j;
                if (l > i) {
                    u64 x = keys[i], y = keys[l];
                    if ((x < y) == ((i & k) == 0)) { keys[i] = y; keys[l] = x; }
                }
                __syncthreads();
            }
            v = keys[t];
#pragma unroll
            for (int j = 16; j >= 1; j >>= 1)
                v = casx(v, j, k, t);
        }
        keys[t] = v;
    }
    __syncthreads();

    // --- build sorted anchors / offset boxes / class; count classes
    int myc = -1;
    if (t < M) {
        unsigned anc = ~(unsigned)(keys[t] & 0xFFFFFFFFULL);
        size_t g = (size_t)b * NN + anc;
        float4 bx = g_cbox[g];
        float  jf = g_cmeta[g].y;
        float off = jf * 4096.0f;   // exact
        obox[t] = make_float4(__fadd_rn(bx.x, off), __fadd_rn(bx.y, off),
                              __fadd_rn(bx.z, off), __fadd_rn(bx.w, off));
        myc = (int)jf;
        cls[t] = (unsigned char)myc;
        sanchor[t] = (int)anc;
        atomicAdd(&ccount[myc], 1);
    }
    __syncthreads();

    // --- warp-0 exclusive prefix over 80 class counts (3 chunks of 32)
    if (t < 32) {
        int carry = 0;
#pragma unroll
        for (int ch = 0; ch < 3; ch++) {
            int c = ch * 32 + t;
            int v = (c < NCLS) ? ccount[c] : 0;
            int inc = v;
#pragma unroll
            for (int off = 1; off < 32; off <<= 1) {
                int u = __shfl_up_sync(0xffffffffu, inc, off);
                if (t >= off) inc += u;
            }
            if (c < NCLS) cbase[c] = inc - v + carry;
            carry += __shfl_sync(0xffffffffu, inc, 31);
        }
    }
    __syncthreads();
    if (t < M) byclass[cbase[myc] + atomicAdd(&cofs[myc], 1)] = t;
    __syncthreads();

    // --- class-segmented pairwise suppression: rank t scans its own class
    //     segment; IoU(offset boxes) > 0.45 with rj > t -> record pair.
    if (t < M) {
        int s0 = cbase[myc], L = ccount[myc];
        float4 bi = obox[t];
        float a1 = __fmul_rn(__fsub_rn(bi.z, bi.x), __fsub_rn(bi.w, bi.y));
        int any = 0;
        for (int p = 0; p < L; p++) {
            int rj = byclass[s0 + p];
            if (rj > t) {
                float4 bj = obox[rj];
                float ltx = fmaxf(bi.x, bj.x), lty = fmaxf(bi.y, bj.y);
                float rbx = fminf(bi.z, bj.z), rby = fminf(bi.w, bj.w);
                float ww = fmaxf(__fsub_rn(rbx, ltx), 0.0f);
                float hh = fmaxf(__fsub_rn(rby, lty), 0.0f);
                float inter = __fmul_rn(ww, hh);
                float a2 = __fmul_rn(__fsub_rn(bj.z, bj.x), __fsub_rn(bj.w, bj.y));
                float den = __fadd_rn(__fsub_rn(__fadd_rn(a1, a2), inter), 1e-9f);
                if (__fdiv_rn(inter, den) > 0.45f) {
                    int p2 = atomicAdd(&s_np, 1);
                    if (p2 < PAIRCAP) pairs[p2] = (t << 10) | rj;
                    any = 1;
                }
            }
        }
        if (any) atomicOr(rflagw + (t >> 6), 1ULL << (t & 63));
    }
    __syncthreads();

    // --- warp-0 greedy scan with optimistic 64-candidate batching
    if (t < 32) {
        int lane = t;
        int P = s_np; if (P > PAIRCAP) P = PAIRCAP;
        u64 rem[MASKW];
#pragma unroll
        for (int i = 0; i < MASKW; i++) rem[i] = 0ULL;
        int nk = 0;
        for (int c = 0; c * 64 < M && nk < MAXDET; c++) {
            int base = c * 64;
            int lim = M - base; if (lim > 64) lim = 64;
            u64 limmask = (lim == 64) ? ~0ULL : ((1ULL << lim) - 1);
            u64 rfl   = rflagw[c];
            u64 alive = ~rem[c] & limmask;
            while (alive && nk < MAXDET) {
                u64 fa = alive & rfl;
                if (!fa) {
                    int cnt  = __popcll(alive);
                    int take = MAXDET - nk; if (take > cnt) take = cnt;
                    for (int s = lane; s < take; s += 32) {
                        int pos = sel64(alive, s);
                        g_picks[b * MAXDET + nk + s] = sanchor[base + pos];
                    }
                    nk += take;
                    alive = 0ULL;
                } else {
                    int f = __ffsll(fa) - 1;
                    u64 pre = alive & ((1ULL << f) - 1);
                    int cnt  = __popcll(pre);
                    int take = MAXDET - nk; if (take > cnt) take = cnt;
                    for (int s = lane; s < take; s += 32) {
                        int pos = sel64(pre, s);
                        g_picks[b * MAXDET + nk + s] = sanchor[base + pos];
                    }
                    nk += take;
                    if (nk < MAXDET) {
                        if (lane == 0)
                            g_picks[b * MAXDET + nk] = sanchor[base + f];
                        nk++;
                        int i = base + f;
                        // apply i's suppressions (lane-parallel over pair list)
                        u64 myrem[MASKW];
#pragma unroll
                        for (int q = 0; q < MASKW; q++) myrem[q] = 0ULL;
                        for (int e = lane; e < P; e += 32) {
                            int pr = pairs[e];
                            if ((pr >> 10) == i) {
                                int jj = pr & 1023;
                                myrem[jj >> 6] |= 1ULL << (jj & 63);
                            }
                        }
#pragma unroll
                        for (int q = 0; q < MASKW; q++) {
                            u64 v = myrem[q];
#pragma unroll
                            for (int off = 16; off >= 1; off >>= 1)
                                v |= __shfl_xor_sync(0xffffffffu, v, off);
                            rem[q] |= v;
                        }
                        alive &= ~((2ULL << f) - 1);  // drop bits <= f
                        alive &= ~rem[c] & limmask;
                    } else {
                        alive = 0ULL;
                    }
                }
            }
        }
        if (lane == 0) g_kept[b] = nk;
    }
}

// ------------------------------------------------------------------
// 5) Output: [dets (B,300,6)] [lg (B,300,80)] [keep (B,300)] as float32.
//    One warp per detection row; logits copied as float4 (both sides 16B-aligned).
__global__ void __launch_bounds__(256) k_out(const float* __restrict__ logits,
                                             float* __restrict__ out) {
    int row  = blockIdx.x * 8 + (threadIdx.x >> 5);   // 0..4799
    int lane = threadIdx.x & 31;
    int b = row / MAXDET, r = row % MAXDET;
    bool on = (r < g_kept[b]);
    int anc = on ? g_picks[b * MAXDET + r] : 0;
    size_t g = (size_t)b * NN + anc;
    if (lane < 6) {
        float x = 0.0f;
        if (on) {
            float4 bx = g_cbox[g];
            float2 m  = g_cmeta[g];
            x = (lane == 0) ? bx.x : (lane == 1) ? bx.y : (lane == 2) ? bx.z :
                (lane == 3) ? bx.w : (lane == 4) ? m.x : m.y;
        }
        out[(size_t)row * 6 + lane] = x;
    } else if (lane == 6) {
        out[412800 + row] = on ? 1.0f : 0.0f;
    }
    if (lane < 20) {   // 20 float4 = 80 floats
        const float4* src = (const float4*)(logits + g * NCLS);
        float4 v = on ? src[lane] : make_float4(0.f, 0.f, 0.f, 0.f);
        ((float4*)(out + 28800 + (size_t)row * NCLS))[lane] = v;
    }
}

// ------------------------------------------------------------------
extern "C" void kernel_launch(void* const* d_in, const int* in_sizes, int n_in,
                              void* d_out, int out_size) {
    (void)in_sizes; (void)n_in; (void)out_size;
    const float* pred   = (const float*)d_in[0];
    const float* logits = (const float*)d_in[1];
    float* out = (float*)d_out;

    const int prep_smem = TILE * ROWW * 4;                           // 43520 B
    const int sm_smem   = CAP * 8 + CAP * 16 + CAP * 4 + CAP * 4
                        + PAIRCAP * 4 + CAP + MASKW * 8;             // 33344 B
    cudaFuncSetAttribute(k_prep,     cudaFuncAttributeMaxDynamicSharedMemorySize, prep_smem);
    cudaFuncSetAttribute(k_sortmask, cudaFuncAttributeMaxDynamicSharedMemorySize, sm_smem);

    k_prep<<<dim3((NN + TILE - 1) / TILE, BB), 256, prep_smem>>>(pred);   // 1
    k_thresh<<<1, 512>>>();                                               // 2
    k_compact<<<dim3((NN + 255) / 256, BB), 256>>>();                     // 3
    k_sortmask<<<BB, CAP, sm_smem>>>();                                   // 4 <- ncu
    k_out<<<BB * MAXDET / 8, 256>>>(logits, out);                         // 5
}

// round 17
// speedup vs baseline: 2.7059x; 1.0691x over previous
#include <cuda_runtime.h>

#define BB      16
#define NN      25200
#define NCLS    80
#define ROWW    85
#define NBUCK   1024
#define CAP     512
#define KSEL    448
#define MAXDET  300
#define MASKW   (CAP / 64)     // 8 u64 words
#define PAIRCAP 4096
#define TILE    128

typedef unsigned long long u64;

// ---- static device scratch (no runtime allocation allowed) ----
__device__ float4 g_cbox[BB * NN];      // xyxy per anchor
__device__ float2 g_cmeta[BB * NN];     // (conf or -1, class as float)
__device__ int    g_hist[BB * NBUCK];   // zero-init; k_thresh restores zeros
__device__ int    g_thresh[BB];
__device__ int    g_selcount[BB];
__device__ u64    g_selkeys[BB * CAP];
__device__ int    g_picks[BB * MAXDET];
__device__ int    g_kept[BB];

__device__ __forceinline__ unsigned su32(const void* p) {
    unsigned r;
    asm("{ .reg .u64 t; cvta.to.shared.u64 t, %1; cvt.u32.u64 %0, t; }"
        : "=r"(r) : "l"(p));
    return r;
}

// ------------------------------------------------------------------
// 1) Preprocess: cp.async staging, per-anchor class argmax, box decode,
//    score histogram.
__global__ void __launch_bounds__(256) k_prep(const float* __restrict__ pred) {
    extern __shared__ float psm[];                 // 128*85 floats = 43520 B
    int b  = blockIdx.y;
    int a0 = blockIdx.x * TILE;
    int rows = NN - a0; if (rows > TILE) rows = TILE;   // 128 or 112, both %4==0
    const float4* gp4 = (const float4*)(pred + ((size_t)b * NN + a0) * ROWW);
    int nvec = rows * ROWW / 4;
    unsigned sbase = su32(psm);
    for (int k = threadIdx.x; k < nvec; k += 256) {
        asm volatile("cp.async.cg.shared.global [%0], [%1], 16;"
                     :: "r"(sbase + k * 16), "l"(gp4 + k));
    }
    asm volatile("cp.async.commit_group;");
    asm volatile("cp.async.wait_group 0;" ::: "memory");
    __syncthreads();

    int t = threadIdx.x;
    if (t < rows) {
        const float* p = psm + t * ROWW;
        float cx = p[0], cy = p[1], w = p[2], h = p[3], obj = p[4];
        float best = -1.0f; int bj = 0;
#pragma unroll 8
        for (int c = 0; c < NCLS; c++) {
            float v = __fmul_rn(p[5 + c], obj);   // same rounding as reference
            if (v > best) { best = v; bj = c; }   // first-max tie-break
        }
        float hw = __fmul_rn(w, 0.5f), hh = __fmul_rn(h, 0.5f);
        float4 box = make_float4(__fsub_rn(cx, hw), __fsub_rn(cy, hh),
                                 __fadd_rn(cx, hw), __fadd_rn(cy, hh));
        bool valid = (obj > 0.25f) && (best > 0.25f);
        size_t g = (size_t)b * NN + a0 + t;
        g_cbox[g]  = box;
        g_cmeta[g] = make_float2(valid ? best : -1.0f, (float)bj);
        if (valid) {
            int bkt = (int)(best * 1024.0f);      // *1024 exact (pow2)
            if (bkt > NBUCK - 1) bkt = NBUCK - 1;
            atomicAdd(&g_hist[b * NBUCK + bkt], 1);
        }
    }
}

// ------------------------------------------------------------------
// 2) Per-image cutoff (warp per image), then restore g_hist zeros and
//    reset g_selcount.
__global__ void __launch_bounds__(512) k_thresh() {
    int w = threadIdx.x >> 5, lane = threadIdx.x & 31;
    int b = w;                                  // 16 warps == BB
    int total = 0, thr = 0;
    for (int c = 0; c < 32; c++) {
        int k = 1023 - (c * 32 + lane);
        int s = g_hist[b * NBUCK + k];
#pragma unroll
        for (int off = 1; off < 32; off <<= 1) {
            int u = __shfl_up_sync(0xffffffffu, s, off);
            if (lane >= off) s += u;
        }
        int S = total + s;
        unsigned bal = __ballot_sync(0xffffffffu, S >= KSEL);
        if (bal) {
            int f  = __ffs(bal) - 1;
            int Sf = __shfl_sync(0xffffffffu, S, f);
            int kk = 1023 - (c * 32 + f);
            thr = (Sf > CAP) ? kk + 1 : kk;      // suffix(kk+1) < KSEL <= CAP
            break;
        }
        total = __shfl_sync(0xffffffffu, S, 31);
    }
    if (lane == 0) { g_thresh[b] = thr; g_selcount[b] = 0; }
    for (int c = 0; c < 32; c++)                 // restore zeros for next replay
        g_hist[b * NBUCK + c * 32 + lane] = 0;
}

// ------------------------------------------------------------------
// 3) Chip-wide compaction with block-aggregated global atomics.
__global__ void __launch_bounds__(256) k_compact() {
    __shared__ int wcnt[8], wbase[8], blkbase;
    int b = blockIdx.y;
    int a = blockIdx.x * 256 + threadIdx.x;
    int w = threadIdx.x >> 5, lane = threadIdx.x & 31;
    bool sel = false; u64 key = 0;
    if (a < NN) {
        float2 m = g_cmeta[(size_t)b * NN + a];
        if (m.x > 0.0f) {
            int bkt = (int)(m.x * 1024.0f);
            if (bkt > NBUCK - 1) bkt = NBUCK - 1;
            if (bkt >= g_thresh[b]) {
                sel = true;
                key = ((u64)__float_as_uint(m.x) << 32) | (u64)(~(unsigned)a);
            }
        }
    }
    unsigned ball = __ballot_sync(0xffffffffu, sel);
    if (lane == 0) wcnt[w] = __popc(ball);
    __syncthreads();
    if (threadIdx.x == 0) {
        int tot = 0;
#pragma unroll
        for (int i = 0; i < 8; i++) { wbase[i] = tot; tot += wcnt[i]; }
        blkbase = tot ? atomicAdd(&g_selcount[b], tot) : 0;
    }
    __syncthreads();
    if (sel) {
        int pos = blkbase + wbase[w] + __popc(ball & ((1u << lane) - 1));
        if (pos < CAP) g_selkeys[b * CAP + pos] = key;   // total provably <= CAP
    }
}

// ------------------------------------------------------------------
// Bitonic compare-exchange via shfl (element per thread), desc final order.
__device__ __forceinline__ u64 casx(u64 v, int j, int k, int t) {
    u64 o = __shfl_xor_sync(0xffffffffu, v, j);
    bool takemax = (((t & j) == 0) == ((t & k) == 0));
    return takemax ? (v > o ? v : o) : (v < o ? v : o);
}

// n-th (0-indexed) set bit of a 64-bit mask
__device__ __forceinline__ int sel64(u64 m, int n) {
    unsigned lo = (unsigned)m, hi = (unsigned)(m >> 32);
    int c = __popc(lo);
    return (n < c) ? (int)__fns(lo, 0, n + 1) : 32 + (int)__fns(hi, 0, n - c + 1);
}

// ------------------------------------------------------------------
// 4) Fused: sort (512 keys) + offset-box build + class-segmented pairwise
//    suppression + warp-0 greedy scan (removed bitset in SMEM — no
//    dynamically-indexed register arrays, no local-memory demotion).
__global__ void __launch_bounds__(CAP, 1) k_sortmask() {
    extern __shared__ char dynsm[];
    u64*           keys    = (u64*)dynsm;                                  // 4KB
    float4*        obox    = (float4*)(dynsm + CAP * 8);                   // 8KB
    int*           byclass = (int*)(dynsm + CAP * 8 + CAP * 16);           // 2KB
    int*           sanchor = byclass + CAP;                                // 2KB
    int*           pairs   = sanchor + CAP;                                // 16KB
    unsigned char* cls     = (unsigned char*)(pairs + PAIRCAP);            // 512B
    u64*           rflagw  = (u64*)(cls + CAP);                            // 64B
    u64*           rem_s   = rflagw + MASKW;                               // 64B
    __shared__ int s_np;
    __shared__ int ccount[NCLS], cbase[NCLS], cofs[NCLS];

    int b = blockIdx.x, t = threadIdx.x;
    if (t == 0) s_np = 0;
    if (t < MASKW) { rflagw[t] = 0ULL; rem_s[t] = 0ULL; }
    if (t < NCLS) { ccount[t] = 0; cofs[t] = 0; }
    int M = g_selcount[b]; if (M > CAP) M = CAP;
    keys[t] = (t < M) ? g_selkeys[b * CAP + t] : 0ULL;
    __syncthreads();

    // --- hybrid bitonic sort (desc): shfl for j<32, SMEM+barrier for j>=32
    {
        u64 v = keys[t];
#pragma unroll
        for (int k = 2; k <= 32; k <<= 1)
#pragma unroll
            for (int j = k >> 1; j >= 1; j >>= 1)
                v = casx(v, j, k, t);
        for (int k = 64; k <= CAP; k <<= 1) {
            keys[t] = v;
            __syncthreads();
            for (int j = k >> 1; j >= 32; j >>= 1) {
                int i = t, l = i ^ j;
                if (l > i) {
                    u64 x = keys[i], y = keys[l];
                    if ((x < y) == ((i & k) == 0)) { keys[i] = y; keys[l] = x; }
                }
                __syncthreads();
            }
            v = keys[t];
#pragma unroll
            for (int j = 16; j >= 1; j >>= 1)
                v = casx(v, j, k, t);
        }
        keys[t] = v;
    }
    __syncthreads();

    // --- build sorted anchors / offset boxes / class; count classes
    int myc = -1;
    if (t < M) {
        unsigned anc = ~(unsigned)(keys[t] & 0xFFFFFFFFULL);
        size_t g = (size_t)b * NN + anc;
        float4 bx = g_cbox[g];
        float  jf = g_cmeta[g].y;
        float off = jf * 4096.0f;   // exact
        obox[t] = make_float4(__fadd_rn(bx.x, off), __fadd_rn(bx.y, off),
                              __fadd_rn(bx.z, off), __fadd_rn(bx.w, off));
        myc = (int)jf;
        cls[t] = (unsigned char)myc;
        sanchor[t] = (int)anc;
        atomicAdd(&ccount[myc], 1);
    }
    __syncthreads();

    // --- warp-0 exclusive prefix over 80 class counts (3 chunks of 32)
    if (t < 32) {
        int carry = 0;
#pragma unroll
        for (int ch = 0; ch < 3; ch++) {
            int c = ch * 32 + t;
            int v = (c < NCLS) ? ccount[c] : 0;
            int inc = v;
#pragma unroll
            for (int off = 1; off < 32; off <<= 1) {
                int u = __shfl_up_sync(0xffffffffu, inc, off);
                if (t >= off) inc += u;
            }
            if (c < NCLS) cbase[c] = inc - v + carry;
            carry += __shfl_sync(0xffffffffu, inc, 31);
        }
    }
    __syncthreads();
    if (t < M) byclass[cbase[myc] + atomicAdd(&cofs[myc], 1)] = t;
    __syncthreads();

    // --- class-segmented pairwise suppression: rank t scans its own class
    //     segment; IoU(offset boxes) > 0.45 with rj > t -> record pair.
    if (t < M) {
        int s0 = cbase[myc], L = ccount[myc];
        float4 bi = obox[t];
        float a1 = __fmul_rn(__fsub_rn(bi.z, bi.x), __fsub_rn(bi.w, bi.y));
        int any = 0;
        for (int p = 0; p < L; p++) {
            int rj = byclass[s0 + p];
            if (rj > t) {
                float4 bj = obox[rj];
                float ltx = fmaxf(bi.x, bj.x), lty = fmaxf(bi.y, bj.y);
                float rbx = fminf(bi.z, bj.z), rby = fminf(bi.w, bj.w);
                float ww = fmaxf(__fsub_rn(rbx, ltx), 0.0f);
                float hh = fmaxf(__fsub_rn(rby, lty), 0.0f);
                float inter = __fmul_rn(ww, hh);
                float a2 = __fmul_rn(__fsub_rn(bj.z, bj.x), __fsub_rn(bj.w, bj.y));
                float den = __fadd_rn(__fsub_rn(__fadd_rn(a1, a2), inter), 1e-9f);
                if (__fdiv_rn(inter, den) > 0.45f) {
                    int p2 = atomicAdd(&s_np, 1);
                    if (p2 < PAIRCAP) pairs[p2] = (t << 10) | rj;
                    any = 1;
                }
            }
        }
        if (any) atomicOr(rflagw + (t >> 6), 1ULL << (t & 63));
    }
    __syncthreads();

    // --- warp-0 greedy scan with optimistic 64-candidate batching;
    //     removed bitset in SMEM (rem_s), suppression via lane-parallel atomicOr
    if (t < 32) {
        int lane = t;
        int P = s_np; if (P > PAIRCAP) P = PAIRCAP;
        int nk = 0;
        for (int c = 0; c * 64 < M && nk < MAXDET; c++) {
            int base = c * 64;
            int lim = M - base; if (lim > 64) lim = 64;
            u64 limmask = (lim == 64) ? ~0ULL : ((1ULL << lim) - 1);
            u64 rfl   = rflagw[c];
            u64 alive = ~rem_s[c] & limmask;
            while (alive && nk < MAXDET) {
                u64 fa = alive & rfl;
                if (!fa) {
                    int cnt  = __popcll(alive);
                    int take = MAXDET - nk; if (take > cnt) take = cnt;
                    for (int s = lane; s < take; s += 32) {
                        int pos = sel64(alive, s);
                        g_picks[b * MAXDET + nk + s] = sanchor[base + pos];
                    }
                    nk += take;
                    alive = 0ULL;
                } else {
                    int f = __ffsll(fa) - 1;
                    u64 pre = alive & ((1ULL << f) - 1);   // alive bits before f
                    int cnt  = __popcll(pre);
                    int take = MAXDET - nk; if (take > cnt) take = cnt;
                    for (int s = lane; s < take; s += 32) {
                        int pos = sel64(pre, s);
                        g_picks[b * MAXDET + nk + s] = sanchor[base + pos];
                    }
                    nk += take;
                    if (nk < MAXDET) {
                        if (lane == 0)
                            g_picks[b * MAXDET + nk] = sanchor[base + f];
                        nk++;
                        int i = base + f;
                        for (int e = lane; e < P; e += 32) {   // apply i's suppressions
                            int pr = pairs[e];
                            if ((pr >> 10) == i) {
                                int jj = pr & 1023;
                                atomicOr(&rem_s[jj >> 6], 1ULL << (jj & 63));
                            }
                        }
                        __syncwarp();
                        alive &= ~((2ULL << f) - 1);   // drop bits <= f
                        alive &= ~rem_s[c] & limmask;  // refresh current word
                    } else {
                        alive = 0ULL;
                    }
                }
            }
        }
        if (lane == 0) g_kept[b] = nk;
    }
}

// ------------------------------------------------------------------
// 5) Output: [dets (B,300,6)] [lg (B,300,80)] [keep (B,300)] as float32.
//    One warp per detection row; logits copied as float4 (both sides 16B-aligned).
__global__ void __launch_bounds__(256) k_out(const float* __restrict__ logits,
                                             float* __restrict__ out) {
    int row  = blockIdx.x * 8 + (threadIdx.x >> 5);   // 0..4799
    int lane = threadIdx.x & 31;
    int b = row / MAXDET, r = row % MAXDET;
    bool on = (r < g_kept[b]);
    int anc = on ? g_picks[b * MAXDET + r] : 0;
    size_t g = (size_t)b * NN + anc;
    if (lane < 6) {
        float x = 0.0f;
        if (on) {
            float4 bx = g_cbox[g];
            float2 m  = g_cmeta[g];
            x = (lane == 0) ? bx.x : (lane == 1) ? bx.y : (lane == 2) ? bx.z :
                (lane == 3) ? bx.w : (lane == 4) ? m.x : m.y;
        }
        out[(size_t)row * 6 + lane] = x;
    } else if (lane == 6) {
        out[412800 + row] = on ? 1.0f : 0.0f;
    }
    if (lane < 20) {   // 20 float4 = 80 floats
        const float4* src = (const float4*)(logits + g * NCLS);
        float4 v = on ? src[lane] : make_float4(0.f, 0.f, 0.f, 0.f);
        ((float4*)(out + 28800 + (size_t)row * NCLS))[lane] = v;
    }
}

// ------------------------------------------------------------------
extern "C" void kernel_launch(void* const* d_in, const int* in_sizes, int n_in,
                              void* d_out, int out_size) {
    (void)in_sizes; (void)n_in; (void)out_size;
    const float* pred   = (const float*)d_in[0];
    const float* logits = (const float*)d_in[1];
    float* out = (float*)d_out;

    const int prep_smem = TILE * ROWW * 4;                           // 43520 B
    const int sm_smem   = CAP * 8 + CAP * 16 + CAP * 4 + CAP * 4
                        + PAIRCAP * 4 + CAP + 2 * MASKW * 8;         // 33408 B
    cudaFuncSetAttribute(k_prep,     cudaFuncAttributeMaxDynamicSharedMemorySize, prep_smem);
    cudaFuncSetAttribute(k_sortmask, cudaFuncAttributeMaxDynamicSharedMemorySize, sm_smem);

    k_prep<<<dim3((NN + TILE - 1) / TILE, BB), 256, prep_smem>>>(pred);   // 1
    k_thresh<<<1, 512>>>();                                               // 2
    k_compact<<<dim3((NN + 255) / 256, BB), 256>>>();                     // 3
    k_sortmask<<<BB, CAP, sm_smem>>>();                                   // 4 <- ncu
    k_out<<<BB * MAXDET / 8, 256>>>(logits, out);                         // 5
}